// round 16
// baseline (speedup 1.0000x reference)
#include <cuda_runtime.h>
#include <cuda_fp16.h>
#include <cuda_bf16.h>
#include <cstdint>

// ---------------- problem constants ----------------
#define DM     1024
#define NLAYER 2
#define VOCAB  32000
#define DS     16
#define DI     2048
#define DR     64
#define DC     4
#define BB     2
#define LL     1024
#define TT     (BB*LL)

// ---------------- device scratch (fp32) ----------------
__device__ float g_x   [TT*DM];
__device__ float g_ir  [TT*2*DI];
__device__ float g_u   [TT*DI];
__device__ float g_xdbl[TT*96];
__device__ float g_dlt [TT*DI];
__device__ float g_part[2*TT*DM];    // split-K partials (covers 8*TT*96 too)

// ---------------- fp16 buffers ----------------
__device__ __half g_emb_f[VOCAB*DM];
__device__ __half g_wlr [NLAYER*2*DI*DM];
__device__ __half g_wx  [NLAYER*96*DI];
__device__ __half g_wdt [NLAYER*DI*DR];
__device__ __half g_wo  [NLAYER*DM*DI];
__device__ __half g_xn_f [TT*DM];
__device__ __half g_u_f  [TT*DI];
__device__ __half g_xd_f [TT*96];
__device__ __half g_y_f  [TT*DI];

// ---------------- helpers ----------------
static __device__ __forceinline__ uint32_t s2u(const void* p) {
    uint32_t a;
    asm("{ .reg .u64 t; cvta.to.shared.u64 t, %1; cvt.u32.u64 %0, t; }" : "=r"(a) : "l"(p));
    return a;
}
static __device__ __forceinline__ void cp16(uint32_t s, const void* g, bool pred) {
    int sz = pred ? 16 : 0;
    asm volatile("cp.async.cg.shared.global [%0], [%1], 16, %2;" :: "r"(s), "l"(g), "r"(sz));
}
#define CP_COMMIT() asm volatile("cp.async.commit_group;" ::: "memory")
#define CP_WAIT1()  asm volatile("cp.async.wait_group 1;"  ::: "memory")

#define LDSM4(r, addr) asm volatile( \
    "ldmatrix.sync.aligned.m8n8.x4.shared.b16 {%0,%1,%2,%3}, [%4];" \
    : "=r"((r)[0]),"=r"((r)[1]),"=r"((r)[2]),"=r"((r)[3]) : "r"(addr))
#define MMA(d, a, b) asm volatile( \
    "mma.sync.aligned.m16n8k16.row.col.f32.f16.f16.f32 " \
    "{%0,%1,%2,%3},{%4,%5,%6,%7},{%8,%9},{%0,%1,%2,%3};" \
    : "+f"((d)[0]),"+f"((d)[1]),"+f"((d)[2]),"+f"((d)[3]) \
    : "r"((a)[0]),"r"((a)[1]),"r"((a)[2]),"r"((a)[3]),"r"((b)[0]),"r"((b)[1]))

// ---------------- mega convert: all weights fp32 -> fp16, one launch ----------------
#define NSEG 11
struct CvtJobs {
    const float* src[NSEG];
    __half*      dst[NSEG];
    int          cum[NSEG+1];
};

__global__ void k_cvt_all(CvtJobs J) {
    int total = J.cum[NSEG];
    for (int v = blockIdx.x * blockDim.x + threadIdx.x; v < total;
         v += gridDim.x * blockDim.x) {
        int seg = 0;
        #pragma unroll
        for (int s = 1; s < NSEG; s++) seg += (v >= J.cum[s]) ? 1 : 0;
        int local = v - J.cum[seg];
        const float4* sp = reinterpret_cast<const float4*>(J.src[seg] + (size_t)local*16);
        __half* dp = J.dst[seg] + (size_t)local*16;
        float4 a = sp[0], b = sp[1], c = sp[2], d = sp[3];
        __half2 h0, h1, h2, h3, h4, h5, h6, h7;
        h0.x = __float2half_rn(a.x); h0.y = __float2half_rn(a.y);
        h1.x = __float2half_rn(a.z); h1.y = __float2half_rn(a.w);
        h2.x = __float2half_rn(b.x); h2.y = __float2half_rn(b.y);
        h3.x = __float2half_rn(b.z); h3.y = __float2half_rn(b.w);
        h4.x = __float2half_rn(c.x); h4.y = __float2half_rn(c.y);
        h5.x = __float2half_rn(c.z); h5.y = __float2half_rn(c.w);
        h6.x = __float2half_rn(d.x); h6.y = __float2half_rn(d.y);
        h7.x = __float2half_rn(d.z); h7.y = __float2half_rn(d.w);
        uint4 o0, o1;
        o0.x = *reinterpret_cast<uint32_t*>(&h0); o0.y = *reinterpret_cast<uint32_t*>(&h1);
        o0.z = *reinterpret_cast<uint32_t*>(&h2); o0.w = *reinterpret_cast<uint32_t*>(&h3);
        o1.x = *reinterpret_cast<uint32_t*>(&h4); o1.y = *reinterpret_cast<uint32_t*>(&h5);
        o1.z = *reinterpret_cast<uint32_t*>(&h6); o1.w = *reinterpret_cast<uint32_t*>(&h7);
        *reinterpret_cast<uint4*>(dp)     = o0;
        *reinterpret_cast<uint4*>(dp + 8) = o1;
    }
}

// ---------------- embed ----------------
__global__ void k_embed(const int* __restrict__ ids, const float* __restrict__ emb) {
    int t = blockIdx.x;
    int id = ids[t];
    for (int c = threadIdx.x; c < DM; c += blockDim.x)
        g_x[t*DM + c] = emb[id*DM + c];
}

// ---------------- rmsnorm -> fp16 ----------------
__global__ void k_rmsnorm(const float* __restrict__ x, const float* __restrict__ w,
                          __half* __restrict__ of) {
    int t = blockIdx.x;
    const float* xr = x + t*DM;
    float s = 0.f;
    for (int c = threadIdx.x; c < DM; c += blockDim.x) { float v = xr[c]; s += v*v; }
    for (int o = 16; o > 0; o >>= 1) s += __shfl_xor_sync(0xffffffffu, s, o);
    __shared__ float red[8];
    int wid = threadIdx.x >> 5, lid = threadIdx.x & 31;
    if (lid == 0) red[wid] = s;
    __syncthreads();
    if (wid == 0) {
        float v = (lid < (blockDim.x >> 5)) ? red[lid] : 0.f;
        for (int o = 4; o > 0; o >>= 1) v += __shfl_xor_sync(0xffffffffu, v, o);
        if (lid == 0) red[0] = v;
    }
    __syncthreads();
    float scale = rsqrtf(red[0] / (float)DM + 1e-5f);
    for (int c = threadIdx.x; c < DM; c += blockDim.x)
        of[t*DM + c] = __float2half_rn(xr[c] * scale * w[c]);
}

// ---------------- HMMA GEMM, BK=64, 3-stage, split-K via blockIdx.z ----------------
#define EPI_NONE     0
#define EPI_SOFTPLUS 1

#define TILE_B   16384
#define OFF_A    0
#define OFF_B    (TILE_B)
#define STAGE_B  (2*TILE_B)
#define NSTAGE   3
#define SMEM_DYN (NSTAGE*STAGE_B)   // 96 KB

__device__ __forceinline__ void load_stage(uint32_t sbase,
        const __half* __restrict__ A, int lda, int m0,
        const __half* __restrict__ Bf, int ldb, int n0, int N, int k0, int tid) {
    #pragma unroll
    for (int it = 0; it < 4; it++) {
        int i = tid + it*256;
        int r = i >> 3;
        int c = i & 7;
        uint32_t off = r*128 + ((c ^ (r & 7)) << 4);
        size_t ga = (size_t)(m0 + r)*lda + k0 + c*8;
        cp16(sbase + OFF_A + off, A + ga, true);
        bool bp = (n0 + r) < N;
        size_t gb = (size_t)(bp ? (n0 + r) : 0)*ldb + k0 + c*8;
        cp16(sbase + OFF_B + off, Bf + gb, bp);
    }
}

template<int EPI>
__global__ void __launch_bounds__(256, 2) k_mma(
        const __half* __restrict__ A, int lda,
        const __half* __restrict__ Bf, int ldb,
        float* __restrict__ C, int ldc, int M, int N, int Kslice,
        const float* __restrict__ R) {
    extern __shared__ __align__(1024) char smem[];
    const uint32_t sb = s2u(smem);
    const int tid = threadIdx.x, lane = tid & 31, wid = tid >> 5;
    const int wm = wid >> 2, wn = wid & 3;
    const int m0 = blockIdx.x * 128, n0 = blockIdx.y * 128;
    const int z = blockIdx.z;
    A  += (size_t)z * Kslice;
    Bf += (size_t)z * Kslice;
    C  += (size_t)z * M * ldc;

    float acc[4][4][4];
    #pragma unroll
    for (int a = 0; a < 4; a++)
        #pragma unroll
        for (int b = 0; b < 4; b++)
            #pragma unroll
            for (int c = 0; c < 4; c++) acc[a][b][c] = 0.f;

    const int NC = Kslice / 64;
    load_stage(sb + 0*STAGE_B, A, lda, m0, Bf, ldb, n0, N, 0, tid);
    CP_COMMIT();
    if (NC > 1)
        load_stage(sb + 1*STAGE_B, A, lda, m0, Bf, ldb, n0, N, 64, tid);
    CP_COMMIT();

    const int arow  = lane & 15;
    const int acb16 = (lane >> 4) & 1;
    const int brow  = lane & 7;
    const int bnt   = (lane >> 4) & 1;
    const int bkh   = (lane >> 3) & 1;

    int stage = 0;
    for (int c = 0; c < NC; c++) {
        CP_WAIT1();
        __syncthreads();
        if (c + 2 < NC) {
            int s2 = stage + 2; if (s2 >= NSTAGE) s2 -= NSTAGE;
            load_stage(sb + s2*STAGE_B, A, lda, m0, Bf, ldb, n0, N, (c + 2)*64, tid);
        }
        CP_COMMIT();

        uint32_t st = sb + stage*STAGE_B;
        #pragma unroll
        for (int kk = 0; kk < 4; kk++) {
            uint32_t bf[4][2], af[4][4];
            #pragma unroll
            for (int p = 0; p < 2; p++) {
                int r = wn*32 + (p*2 + bnt)*8 + brow;
                uint32_t off = r*128 + (((kk*2 + bkh) ^ (r & 7)) << 4);
                uint32_t t[4];
                LDSM4(t, st + OFF_B + off);
                bf[2*p][0] = t[0]; bf[2*p][1] = t[1];
                bf[2*p+1][0] = t[2]; bf[2*p+1][1] = t[3];
            }
            #pragma unroll
            for (int mt = 0; mt < 4; mt++) {
                int r = wm*64 + mt*16 + arow;
                uint32_t off = r*128 + (((kk*2 + acb16) ^ (r & 7)) << 4);
                LDSM4(af[mt], st + OFF_A + off);
            }
            #pragma unroll
            for (int mt = 0; mt < 4; mt++)
                #pragma unroll
                for (int nt = 0; nt < 4; nt++)
                    MMA(acc[mt][nt], af[mt], bf[nt]);
        }
        stage++; if (stage >= NSTAGE) stage = 0;
    }

    #pragma unroll
    for (int mt = 0; mt < 4; mt++) {
        #pragma unroll
        for (int nt = 0; nt < 4; nt++) {
            int row = m0 + wm*64 + mt*16 + (lane >> 2);
            int col = n0 + wn*32 + nt*8 + (lane & 3)*2;
            if (col < N) {
                #pragma unroll
                for (int h = 0; h < 2; h++) {
                    int rr = row + h*8;
                    float v0 = acc[mt][nt][2*h + 0];
                    float v1 = acc[mt][nt][2*h + 1];
                    if (EPI == EPI_SOFTPLUS) {
                        v0 = (v0 > 20.f) ? v0 : log1pf(expf(v0));
                        v1 = (v1 > 20.f) ? v1 : log1pf(expf(v1));
                    }
                    *reinterpret_cast<float2*>(&C[(size_t)rr*ldc + col]) = make_float2(v0, v1);
                }
            }
        }
    }
}

// ---------------- split-K reducers ----------------
__global__ void k_redx(const float* __restrict__ part) {
    int i = blockIdx.x * blockDim.x + threadIdx.x;
    if (i >= TT*96) return;
    float s = 0.f;
    #pragma unroll
    for (int z = 0; z < 8; z++) s += part[(size_t)z*TT*96 + i];
    g_xdbl[i] = s;
    g_xd_f[i] = __float2half_rn(s);
}
__global__ void k_redadd(const float* __restrict__ part) {
    int i = blockIdx.x * blockDim.x + threadIdx.x;
    if (i >= TT*DM) return;
    g_x[i] = part[i] + part[(size_t)TT*DM + i] + g_x[i];
}

// ---------------- depthwise causal conv + bias + SiLU, 4 channels/thread ----------------
__global__ void k_conv_silu(const float* __restrict__ cw, const float* __restrict__ cb) {
    int v = blockIdx.x * blockDim.x + threadIdx.x;
    if (v >= TT*DI/4) return;
    int dq = v % (DI/4);
    int d4 = dq * 4;
    int l  = (v / (DI/4)) % LL;
    int b  = v / ((DI/4)*LL);

    float4 c0 = *reinterpret_cast<const float4*>(cw + (d4+0)*DC);
    float4 c1 = *reinterpret_cast<const float4*>(cw + (d4+1)*DC);
    float4 c2 = *reinterpret_cast<const float4*>(cw + (d4+2)*DC);
    float4 c3 = *reinterpret_cast<const float4*>(cw + (d4+3)*DC);
    float4 bias = *reinterpret_cast<const float4*>(cb + d4);

    float4 r[4];
    #pragma unroll
    for (int j = 0; j < 4; j++) {
        int ll = l - (DC-1) + j;
        r[j] = (ll >= 0)
            ? *reinterpret_cast<const float4*>(&g_ir[((size_t)b*LL + ll)*(2*DI) + d4])
            : make_float4(0.f, 0.f, 0.f, 0.f);
    }
    float4 acc;
    acc.x = bias.x + c0.x*r[0].x + c0.y*r[1].x + c0.z*r[2].x + c0.w*r[3].x;
    acc.y = bias.y + c1.x*r[0].y + c1.y*r[1].y + c1.z*r[2].y + c1.w*r[3].y;
    acc.z = bias.z + c2.x*r[0].z + c2.y*r[1].z + c2.z*r[2].z + c2.w*r[3].z;
    acc.w = bias.w + c3.x*r[0].w + c3.y*r[1].w + c3.z*r[2].w + c3.w*r[3].w;

    float4 s;
    s.x = acc.x / (1.f + __expf(-acc.x));
    s.y = acc.y / (1.f + __expf(-acc.y));
    s.z = acc.z / (1.f + __expf(-acc.z));
    s.w = acc.w / (1.f + __expf(-acc.w));

    size_t o = (size_t)(b*LL + l)*DI + d4;
    *reinterpret_cast<float4*>(g_u + o) = s;
    __half2 h0, h1;
    h0.x = __float2half_rn(s.x); h0.y = __float2half_rn(s.y);
    h1.x = __float2half_rn(s.z); h1.y = __float2half_rn(s.w);
    uint2 hp;
    hp.x = *reinterpret_cast<uint32_t*>(&h0);
    hp.y = *reinterpret_cast<uint32_t*>(&h1);
    *reinterpret_cast<uint2*>(g_u_f + o) = hp;
}

// ---------------- selective scan + gate, 8-step batched, 512 thr (1 block/SM) ----------------
__global__ void k_scan(const float* __restrict__ A_log, const float* __restrict__ Dp) {
    int lane = threadIdx.x & 15;
    int grp  = threadIdx.x >> 4;            // 0..31 channels per block
    int ch   = blockIdx.x * 32 + grp;
    int b = ch / DI, d = ch % DI;

    float An = -__expf(A_log[d*DS + lane]);
    float Dv = Dp[d];
    float xs = 0.f;

    for (int l0 = 0; l0 < LL; l0 += 8) {
        float dlt[8], uu[8], Bn[8], Cn[8], dA[8], yv[8];
        #pragma unroll
        for (int j = 0; j < 8; j++) {
            size_t tok = (size_t)(b*LL + l0 + j);
            dlt[j] = g_dlt[tok*DI + d];
            uu[j]  = g_u  [tok*DI + d];
            Bn[j]  = g_xdbl[tok*96 + 64 + lane];
            Cn[j]  = g_xdbl[tok*96 + 80 + lane];
        }
        #pragma unroll
        for (int j = 0; j < 8; j++) dA[j] = __expf(dlt[j] * An);
        #pragma unroll
        for (int j = 0; j < 8; j++) {
            xs = fmaf(dA[j], xs, dlt[j] * uu[j] * Bn[j]);
            yv[j] = xs * Cn[j];
        }
        #pragma unroll
        for (int o = 8; o > 0; o >>= 1) {
            #pragma unroll
            for (int j = 0; j < 8; j++)
                yv[j] += __shfl_xor_sync(0xffffffffu, yv[j], o);
        }
        if (lane == 0) {
            #pragma unroll
            for (int j = 0; j < 8; j++) {
                size_t tok = (size_t)(b*LL + l0 + j);
                float r = g_ir[tok*(2*DI) + DI + d];
                float gate = r / (1.f + __expf(-r));
                g_y_f[tok*DI + d] = __float2half_rn((yv[j] + uu[j] * Dv) * gate);
            }
        }
    }
}

// ---------------- launch ----------------
extern "C" void kernel_launch(void* const* d_in, const int* in_sizes, int n_in,
                              void* d_out, int out_size) {
    const int*   ids      = (const int*)  d_in[0];
    const float* emb      = (const float*)d_in[1];
    const float* norm_f_w = (const float*)d_in[2];
    const float* W_in_l   = (const float*)d_in[3];
    const float* W_in_r   = (const float*)d_in[4];
    const float* conv_w   = (const float*)d_in[5];
    const float* conv_b   = (const float*)d_in[6];
    const float* W_x      = (const float*)d_in[7];
    const float* W_dt     = (const float*)d_in[8];
    const float* A_log    = (const float*)d_in[9];
    const float* Dp       = (const float*)d_in[10];
    const float* W_out    = (const float*)d_in[11];
    const float* norm_w   = (const float*)d_in[12];
    float* out = (float*)d_out;

    float *p_x, *p_ir, *p_u, *p_dlt, *p_part;
    cudaGetSymbolAddress((void**)&p_x,    g_x);
    cudaGetSymbolAddress((void**)&p_ir,   g_ir);
    cudaGetSymbolAddress((void**)&p_u,    g_u);
    cudaGetSymbolAddress((void**)&p_dlt,  g_dlt);
    cudaGetSymbolAddress((void**)&p_part, g_part);

    __half *p_ef, *p_wlr, *p_wx, *p_wdt, *p_wo, *p_xnf, *p_uf, *p_xdf, *p_yf;
    cudaGetSymbolAddress((void**)&p_ef,  g_emb_f);
    cudaGetSymbolAddress((void**)&p_wlr, g_wlr);
    cudaGetSymbolAddress((void**)&p_wx,  g_wx);
    cudaGetSymbolAddress((void**)&p_wdt, g_wdt);
    cudaGetSymbolAddress((void**)&p_wo,  g_wo);
    cudaGetSymbolAddress((void**)&p_xnf, g_xn_f);
    cudaGetSymbolAddress((void**)&p_uf,  g_u_f);
    cudaGetSymbolAddress((void**)&p_xdf, g_xd_f);
    cudaGetSymbolAddress((void**)&p_yf,  g_y_f);

    cudaFuncSetAttribute(k_mma<EPI_NONE>,     cudaFuncAttributeMaxDynamicSharedMemorySize, SMEM_DYN);
    cudaFuncSetAttribute(k_mma<EPI_SOFTPLUS>, cudaFuncAttributeMaxDynamicSharedMemorySize, SMEM_DYN);

    // ---- mega convert job table ----
    CvtJobs J;
    int idx = 0, cum = 0;
    auto add = [&](const float* s, __half* d, int n) {
        J.src[idx] = s; J.dst[idx] = d; J.cum[idx] = cum; cum += n/16; idx++;
    };
    J.cum[0] = 0;
    add(emb, p_ef, VOCAB*DM);
    for (int i = 0; i < NLAYER; i++) {
        add(W_in_l + (size_t)i*DI*DM, p_wlr + (size_t)i*2*DI*DM,           DI*DM);
        add(W_in_r + (size_t)i*DI*DM, p_wlr + (size_t)i*2*DI*DM + DI*DM,   DI*DM);
        add(W_x    + (size_t)i*96*DI, p_wx  + (size_t)i*96*DI,             96*DI);
        add(W_dt   + (size_t)i*DI*DR, p_wdt + (size_t)i*DI*DR,             DI*DR);
        add(W_out  + (size_t)i*DM*DI, p_wo  + (size_t)i*DM*DI,             DM*DI);
    }
    J.cum[NSEG] = cum;

    k_cvt_all<<<2368, 256>>>(J);                                   // 0
    k_embed<<<TT, 256>>>(ids, emb);                                // 1

    for (int i = 0; i < NLAYER; i++) {
        const float* cw  = conv_w + (size_t)i*DI*DC;
        const float* cb  = conv_b + (size_t)i*DI;
        const float* Al  = A_log  + (size_t)i*DI*DS;
        const float* Dpi = Dp     + (size_t)i*DI;
        const float* nw  = norm_w + (size_t)i*DM;
        __half* wlr = p_wlr + (size_t)i*2*DI*DM;
        __half* wx  = p_wx  + (size_t)i*96*DI;
        __half* wdt = p_wdt + (size_t)i*DI*DR;
        __half* wo  = p_wo  + (size_t)i*DM*DI;

        k_rmsnorm<<<TT, 256>>>(p_x, nw, p_xnf);                    // 2 (i=0)
        // 3 (i=0): fused in-proj GEMM <-- ncu capture control
        k_mma<EPI_NONE><<<dim3(TT/128, 2*DI/128, 1), 256, SMEM_DYN>>>(
            p_xnf, DM, wlr, DM, p_ir, 2*DI, TT, 2*DI, DM, nullptr);

        k_conv_silu<<<(TT*DI/4 + 255)/256, 256>>>(cw, cb);

        // x_dbl = u @ Wx^T  split-K x8 (Kslice=256)
        k_mma<EPI_NONE><<<dim3(TT/128, 1, 8), 256, SMEM_DYN>>>(
            p_uf, DI, wx, DI, p_part, 96, TT, 96, DI/8, nullptr);
        k_redx<<<(TT*96 + 255)/256, 256>>>(p_part);

        // delta = softplus(x_dbl[:, :64] @ Wdt^T)  (K=64)
        k_mma<EPI_SOFTPLUS><<<dim3(TT/128, DI/128, 1), 256, SMEM_DYN>>>(
            p_xdf, 96, wdt, DR, p_dlt, DI, TT, DI, DR, nullptr);

        k_scan<<<(BB*DI)/32, 512>>>(Al, Dpi);

        // out-proj split-K x2 (Kslice=1024) + residual reduce
        k_mma<EPI_NONE><<<dim3(TT/128, DM/128, 2), 256, SMEM_DYN>>>(
            p_yf, DI, wo, DI, p_part, DM, TT, DM, DI/2, nullptr);
        k_redadd<<<(TT*DM + 255)/256, 256>>>(p_part);
    }

    // final norm + logits
    k_rmsnorm<<<TT, 256>>>(p_x, norm_f_w, p_xnf);
    k_mma<EPI_NONE><<<dim3(TT/128, VOCAB/128, 1), 256, SMEM_DYN>>>(
        p_xnf, DM, p_ef, DM, out, VOCAB, TT, VOCAB, DM, nullptr);
}

// round 17
// speedup vs baseline: 1.1721x; 1.1721x over previous
#include <cuda_runtime.h>
#include <cuda_fp16.h>
#include <cuda_bf16.h>
#include <cstdint>

// ---------------- problem constants ----------------
#define DM     1024
#define NLAYER 2
#define VOCAB  32000
#define DS     16
#define DI     2048
#define DR     64
#define DC     4
#define BB     2
#define LL     1024
#define TT     (BB*LL)

// ---------------- device scratch ----------------
__device__ float  g_x   [TT*DM];
__device__ __half g_ir_h[TT*2*DI];      // fp16 [xi | res]
__device__ float  g_xdbl[TT*96];
__device__ float  g_dlt [TT*DI];
__device__ float  g_part[2*TT*DM];      // split-K partials (covers 8*TT*96 too)

// ---------------- fp16 buffers ----------------
__device__ __half g_emb_f[VOCAB*DM];
__device__ __half g_wlr [NLAYER*2*DI*DM];
__device__ __half g_wx  [NLAYER*96*DI];
__device__ __half g_wdt [NLAYER*DI*DR];
__device__ __half g_wo  [NLAYER*DM*DI];
__device__ __half g_xn_f [TT*DM];
__device__ __half g_u_f  [TT*DI];
__device__ __half g_xd_f [TT*96];
__device__ __half g_y_f  [TT*DI];

// ---------------- helpers ----------------
static __device__ __forceinline__ uint32_t s2u(const void* p) {
    uint32_t a;
    asm("{ .reg .u64 t; cvta.to.shared.u64 t, %1; cvt.u32.u64 %0, t; }" : "=r"(a) : "l"(p));
    return a;
}
static __device__ __forceinline__ void cp16(uint32_t s, const void* g, bool pred) {
    int sz = pred ? 16 : 0;
    asm volatile("cp.async.cg.shared.global [%0], [%1], 16, %2;" :: "r"(s), "l"(g), "r"(sz));
}
#define CP_COMMIT() asm volatile("cp.async.commit_group;" ::: "memory")
#define CP_WAIT1()  asm volatile("cp.async.wait_group 1;"  ::: "memory")

#define LDSM4(r, addr) asm volatile( \
    "ldmatrix.sync.aligned.m8n8.x4.shared.b16 {%0,%1,%2,%3}, [%4];" \
    : "=r"((r)[0]),"=r"((r)[1]),"=r"((r)[2]),"=r"((r)[3]) : "r"(addr))
#define MMA(d, a, b) asm volatile( \
    "mma.sync.aligned.m16n8k16.row.col.f32.f16.f16.f32 " \
    "{%0,%1,%2,%3},{%4,%5,%6,%7},{%8,%9},{%0,%1,%2,%3};" \
    : "+f"((d)[0]),"+f"((d)[1]),"+f"((d)[2]),"+f"((d)[3]) \
    : "r"((a)[0]),"r"((a)[1]),"r"((a)[2]),"r"((a)[3]),"r"((b)[0]),"r"((b)[1]))

// ---------------- mega convert: all weights fp32 -> fp16, one launch ----------------
#define NSEG 11
struct CvtJobs {
    const float* src[NSEG];
    __half*      dst[NSEG];
    int          cum[NSEG+1];
};

__global__ void k_cvt_all(CvtJobs J) {
    int total = J.cum[NSEG];
    for (int v = blockIdx.x * blockDim.x + threadIdx.x; v < total;
         v += gridDim.x * blockDim.x) {
        int seg = 0;
        #pragma unroll
        for (int s = 1; s < NSEG; s++) seg += (v >= J.cum[s]) ? 1 : 0;
        int local = v - J.cum[seg];
        const float4* sp = reinterpret_cast<const float4*>(J.src[seg] + (size_t)local*16);
        __half* dp = J.dst[seg] + (size_t)local*16;
        float4 a = sp[0], b = sp[1], c = sp[2], d = sp[3];
        __half2 h0, h1, h2, h3, h4, h5, h6, h7;
        h0.x = __float2half_rn(a.x); h0.y = __float2half_rn(a.y);
        h1.x = __float2half_rn(a.z); h1.y = __float2half_rn(a.w);
        h2.x = __float2half_rn(b.x); h2.y = __float2half_rn(b.y);
        h3.x = __float2half_rn(b.z); h3.y = __float2half_rn(b.w);
        h4.x = __float2half_rn(c.x); h4.y = __float2half_rn(c.y);
        h5.x = __float2half_rn(c.z); h5.y = __float2half_rn(c.w);
        h6.x = __float2half_rn(d.x); h6.y = __float2half_rn(d.y);
        h7.x = __float2half_rn(d.z); h7.y = __float2half_rn(d.w);
        uint4 o0, o1;
        o0.x = *reinterpret_cast<uint32_t*>(&h0); o0.y = *reinterpret_cast<uint32_t*>(&h1);
        o0.z = *reinterpret_cast<uint32_t*>(&h2); o0.w = *reinterpret_cast<uint32_t*>(&h3);
        o1.x = *reinterpret_cast<uint32_t*>(&h4); o1.y = *reinterpret_cast<uint32_t*>(&h5);
        o1.z = *reinterpret_cast<uint32_t*>(&h6); o1.w = *reinterpret_cast<uint32_t*>(&h7);
        *reinterpret_cast<uint4*>(dp)     = o0;
        *reinterpret_cast<uint4*>(dp + 8) = o1;
    }
}

// ---------------- embed ----------------
__global__ void k_embed(const int* __restrict__ ids, const float* __restrict__ emb) {
    int t = blockIdx.x;
    int id = ids[t];
    for (int c = threadIdx.x; c < DM; c += blockDim.x)
        g_x[t*DM + c] = emb[id*DM + c];
}

// ---------------- rmsnorm -> fp16 ----------------
__global__ void k_rmsnorm(const float* __restrict__ x, const float* __restrict__ w,
                          __half* __restrict__ of) {
    int t = blockIdx.x;
    const float* xr = x + t*DM;
    float s = 0.f;
    for (int c = threadIdx.x; c < DM; c += blockDim.x) { float v = xr[c]; s += v*v; }
    for (int o = 16; o > 0; o >>= 1) s += __shfl_xor_sync(0xffffffffu, s, o);
    __shared__ float red[8];
    int wid = threadIdx.x >> 5, lid = threadIdx.x & 31;
    if (lid == 0) red[wid] = s;
    __syncthreads();
    if (wid == 0) {
        float v = (lid < (blockDim.x >> 5)) ? red[lid] : 0.f;
        for (int o = 4; o > 0; o >>= 1) v += __shfl_xor_sync(0xffffffffu, v, o);
        if (lid == 0) red[0] = v;
    }
    __syncthreads();
    float scale = rsqrtf(red[0] / (float)DM + 1e-5f);
    for (int c = threadIdx.x; c < DM; c += blockDim.x)
        of[t*DM + c] = __float2half_rn(xr[c] * scale * w[c]);
}

// ---------------- HMMA GEMM, BK=64, 3-stage, split-K via blockIdx.z ----------------
#define EPI_NONE     0
#define EPI_SOFTPLUS 1
#define EPI_HALF     2

#define TILE_B   16384
#define OFF_A    0
#define OFF_B    (TILE_B)
#define STAGE_B  (2*TILE_B)
#define NSTAGE   3
#define SMEM_DYN (NSTAGE*STAGE_B)   // 96 KB

__device__ __forceinline__ void load_stage(uint32_t sbase,
        const __half* __restrict__ A, int lda, int m0,
        const __half* __restrict__ Bf, int ldb, int n0, int N, int k0, int tid) {
    #pragma unroll
    for (int it = 0; it < 4; it++) {
        int i = tid + it*256;
        int r = i >> 3;
        int c = i & 7;
        uint32_t off = r*128 + ((c ^ (r & 7)) << 4);
        size_t ga = (size_t)(m0 + r)*lda + k0 + c*8;
        cp16(sbase + OFF_A + off, A + ga, true);
        bool bp = (n0 + r) < N;
        size_t gb = (size_t)(bp ? (n0 + r) : 0)*ldb + k0 + c*8;
        cp16(sbase + OFF_B + off, Bf + gb, bp);
    }
}

template<int EPI>
__global__ void __launch_bounds__(256, 2) k_mma(
        const __half* __restrict__ A, int lda,
        const __half* __restrict__ Bf, int ldb,
        float* __restrict__ C, int ldc, int M, int N, int Kslice,
        const float* __restrict__ R) {
    extern __shared__ __align__(1024) char smem[];
    const uint32_t sb = s2u(smem);
    const int tid = threadIdx.x, lane = tid & 31, wid = tid >> 5;
    const int wm = wid >> 2, wn = wid & 3;
    const int m0 = blockIdx.x * 128, n0 = blockIdx.y * 128;
    const int z = blockIdx.z;
    A  += (size_t)z * Kslice;
    Bf += (size_t)z * Kslice;
    C  += (size_t)z * M * ldc;

    float acc[4][4][4];
    #pragma unroll
    for (int a = 0; a < 4; a++)
        #pragma unroll
        for (int b = 0; b < 4; b++)
            #pragma unroll
            for (int c = 0; c < 4; c++) acc[a][b][c] = 0.f;

    const int NC = Kslice / 64;
    load_stage(sb + 0*STAGE_B, A, lda, m0, Bf, ldb, n0, N, 0, tid);
    CP_COMMIT();
    if (NC > 1)
        load_stage(sb + 1*STAGE_B, A, lda, m0, Bf, ldb, n0, N, 64, tid);
    CP_COMMIT();

    const int arow  = lane & 15;
    const int acb16 = (lane >> 4) & 1;
    const int brow  = lane & 7;
    const int bnt   = (lane >> 4) & 1;
    const int bkh   = (lane >> 3) & 1;

    int stage = 0;
    for (int c = 0; c < NC; c++) {
        CP_WAIT1();
        __syncthreads();
        if (c + 2 < NC) {
            int s2 = stage + 2; if (s2 >= NSTAGE) s2 -= NSTAGE;
            load_stage(sb + s2*STAGE_B, A, lda, m0, Bf, ldb, n0, N, (c + 2)*64, tid);
        }
        CP_COMMIT();

        uint32_t st = sb + stage*STAGE_B;
        #pragma unroll
        for (int kk = 0; kk < 4; kk++) {
            uint32_t bf[4][2], af[4][4];
            #pragma unroll
            for (int p = 0; p < 2; p++) {
                int r = wn*32 + (p*2 + bnt)*8 + brow;
                uint32_t off = r*128 + (((kk*2 + bkh) ^ (r & 7)) << 4);
                uint32_t t[4];
                LDSM4(t, st + OFF_B + off);
                bf[2*p][0] = t[0]; bf[2*p][1] = t[1];
                bf[2*p+1][0] = t[2]; bf[2*p+1][1] = t[3];
            }
            #pragma unroll
            for (int mt = 0; mt < 4; mt++) {
                int r = wm*64 + mt*16 + arow;
                uint32_t off = r*128 + (((kk*2 + acb16) ^ (r & 7)) << 4);
                LDSM4(af[mt], st + OFF_A + off);
            }
            #pragma unroll
            for (int mt = 0; mt < 4; mt++)
                #pragma unroll
                for (int nt = 0; nt < 4; nt++)
                    MMA(acc[mt][nt], af[mt], bf[nt]);
        }
        stage++; if (stage >= NSTAGE) stage = 0;
    }

    #pragma unroll
    for (int mt = 0; mt < 4; mt++) {
        #pragma unroll
        for (int nt = 0; nt < 4; nt++) {
            int row = m0 + wm*64 + mt*16 + (lane >> 2);
            int col = n0 + wn*32 + nt*8 + (lane & 3)*2;
            if (col < N) {
                #pragma unroll
                for (int h = 0; h < 2; h++) {
                    int rr = row + h*8;
                    float v0 = acc[mt][nt][2*h + 0];
                    float v1 = acc[mt][nt][2*h + 1];
                    if (EPI == EPI_SOFTPLUS) {
                        v0 = (v0 > 20.f) ? v0 : log1pf(expf(v0));
                        v1 = (v1 > 20.f) ? v1 : log1pf(expf(v1));
                    }
                    if (EPI == EPI_HALF) {
                        __half2 hv;
                        hv.x = __float2half_rn(v0);
                        hv.y = __float2half_rn(v1);
                        *reinterpret_cast<__half2*>(
                            &reinterpret_cast<__half*>(C)[(size_t)rr*ldc + col]) = hv;
                    } else {
                        *reinterpret_cast<float2*>(&C[(size_t)rr*ldc + col]) = make_float2(v0, v1);
                    }
                }
            }
        }
    }
}

// ---------------- split-K reducers ----------------
__global__ void k_redx(const float* __restrict__ part) {
    int i = blockIdx.x * blockDim.x + threadIdx.x;
    if (i >= TT*96) return;
    float s = 0.f;
    #pragma unroll
    for (int z = 0; z < 8; z++) s += part[(size_t)z*TT*96 + i];
    g_xdbl[i] = s;
    g_xd_f[i] = __float2half_rn(s);
}
__global__ void k_redadd(const float* __restrict__ part) {
    int i = blockIdx.x * blockDim.x + threadIdx.x;
    if (i >= TT*DM) return;
    g_x[i] = part[i] + part[(size_t)TT*DM + i] + g_x[i];
}

// ---------------- depthwise causal conv + bias + SiLU (fp16 in/out), 4 ch/thread ----------------
__global__ void k_conv_silu(const float* __restrict__ cw, const float* __restrict__ cb) {
    int v = blockIdx.x * blockDim.x + threadIdx.x;
    if (v >= TT*DI/4) return;
    int dq = v % (DI/4);
    int d4 = dq * 4;
    int l  = (v / (DI/4)) % LL;
    int b  = v / ((DI/4)*LL);

    float4 c0 = *reinterpret_cast<const float4*>(cw + (d4+0)*DC);
    float4 c1 = *reinterpret_cast<const float4*>(cw + (d4+1)*DC);
    float4 c2 = *reinterpret_cast<const float4*>(cw + (d4+2)*DC);
    float4 c3 = *reinterpret_cast<const float4*>(cw + (d4+3)*DC);
    float4 bias = *reinterpret_cast<const float4*>(cb + d4);

    float4 r[4];
    #pragma unroll
    for (int j = 0; j < 4; j++) {
        int ll = l - (DC-1) + j;
        if (ll >= 0) {
            uint2 p = *reinterpret_cast<const uint2*>(
                &g_ir_h[((size_t)b*LL + ll)*(2*DI) + d4]);
            __half2 ph0 = *reinterpret_cast<__half2*>(&p.x);
            __half2 ph1 = *reinterpret_cast<__half2*>(&p.y);
            r[j] = make_float4(__half2float(ph0.x), __half2float(ph0.y),
                               __half2float(ph1.x), __half2float(ph1.y));
        } else {
            r[j] = make_float4(0.f, 0.f, 0.f, 0.f);
        }
    }
    float4 acc;
    acc.x = bias.x + c0.x*r[0].x + c0.y*r[1].x + c0.z*r[2].x + c0.w*r[3].x;
    acc.y = bias.y + c1.x*r[0].y + c1.y*r[1].y + c1.z*r[2].y + c1.w*r[3].y;
    acc.z = bias.z + c2.x*r[0].z + c2.y*r[1].z + c2.z*r[2].z + c2.w*r[3].z;
    acc.w = bias.w + c3.x*r[0].w + c3.y*r[1].w + c3.z*r[2].w + c3.w*r[3].w;

    float4 s;
    s.x = acc.x / (1.f + __expf(-acc.x));
    s.y = acc.y / (1.f + __expf(-acc.y));
    s.z = acc.z / (1.f + __expf(-acc.z));
    s.w = acc.w / (1.f + __expf(-acc.w));

    size_t o = (size_t)(b*LL + l)*DI + d4;
    __half2 h0, h1;
    h0.x = __float2half_rn(s.x); h0.y = __float2half_rn(s.y);
    h1.x = __float2half_rn(s.z); h1.y = __float2half_rn(s.w);
    uint2 hp;
    hp.x = *reinterpret_cast<uint32_t*>(&h0);
    hp.y = *reinterpret_cast<uint32_t*>(&h1);
    *reinterpret_cast<uint2*>(g_u_f + o) = hp;
}

// ---------------- selective scan + gate, 8-step batched, 256 thr ----------------
__global__ void k_scan(const float* __restrict__ A_log, const float* __restrict__ Dp) {
    int lane = threadIdx.x & 15;
    int grp  = threadIdx.x >> 4;
    int ch   = blockIdx.x * 16 + grp;
    int b = ch / DI, d = ch % DI;

    float An = -__expf(A_log[d*DS + lane]);
    float Dv = Dp[d];
    float xs = 0.f;

    for (int l0 = 0; l0 < LL; l0 += 8) {
        float dlt[8], uu[8], Bn[8], Cn[8], dA[8], yv[8];
        #pragma unroll
        for (int j = 0; j < 8; j++) {
            size_t tok = (size_t)(b*LL + l0 + j);
            dlt[j] = g_dlt[tok*DI + d];
            uu[j]  = __half2float(g_u_f[tok*DI + d]);
            Bn[j]  = g_xdbl[tok*96 + 64 + lane];
            Cn[j]  = g_xdbl[tok*96 + 80 + lane];
        }
        #pragma unroll
        for (int j = 0; j < 8; j++) dA[j] = __expf(dlt[j] * An);
        #pragma unroll
        for (int j = 0; j < 8; j++) {
            xs = fmaf(dA[j], xs, dlt[j] * uu[j] * Bn[j]);
            yv[j] = xs * Cn[j];
        }
        #pragma unroll
        for (int o = 8; o > 0; o >>= 1) {
            #pragma unroll
            for (int j = 0; j < 8; j++)
                yv[j] += __shfl_xor_sync(0xffffffffu, yv[j], o);
        }
        if (lane == 0) {
            #pragma unroll
            for (int j = 0; j < 8; j++) {
                size_t tok = (size_t)(b*LL + l0 + j);
                float r = __half2float(g_ir_h[tok*(2*DI) + DI + d]);
                float gate = r / (1.f + __expf(-r));
                g_y_f[tok*DI + d] = __float2half_rn((yv[j] + uu[j] * Dv) * gate);
            }
        }
    }
}

// ---------------- launch ----------------
extern "C" void kernel_launch(void* const* d_in, const int* in_sizes, int n_in,
                              void* d_out, int out_size) {
    const int*   ids      = (const int*)  d_in[0];
    const float* emb      = (const float*)d_in[1];
    const float* norm_f_w = (const float*)d_in[2];
    const float* W_in_l   = (const float*)d_in[3];
    const float* W_in_r   = (const float*)d_in[4];
    const float* conv_w   = (const float*)d_in[5];
    const float* conv_b   = (const float*)d_in[6];
    const float* W_x      = (const float*)d_in[7];
    const float* W_dt     = (const float*)d_in[8];
    const float* A_log    = (const float*)d_in[9];
    const float* Dp       = (const float*)d_in[10];
    const float* W_out    = (const float*)d_in[11];
    const float* norm_w   = (const float*)d_in[12];
    float* out = (float*)d_out;

    float *p_x, *p_dlt, *p_part;
    cudaGetSymbolAddress((void**)&p_x,    g_x);
    cudaGetSymbolAddress((void**)&p_dlt,  g_dlt);
    cudaGetSymbolAddress((void**)&p_part, g_part);

    __half *p_irh, *p_ef, *p_wlr, *p_wx, *p_wdt, *p_wo, *p_xnf, *p_uf, *p_xdf, *p_yf;
    cudaGetSymbolAddress((void**)&p_irh, g_ir_h);
    cudaGetSymbolAddress((void**)&p_ef,  g_emb_f);
    cudaGetSymbolAddress((void**)&p_wlr, g_wlr);
    cudaGetSymbolAddress((void**)&p_wx,  g_wx);
    cudaGetSymbolAddress((void**)&p_wdt, g_wdt);
    cudaGetSymbolAddress((void**)&p_wo,  g_wo);
    cudaGetSymbolAddress((void**)&p_xnf, g_xn_f);
    cudaGetSymbolAddress((void**)&p_uf,  g_u_f);
    cudaGetSymbolAddress((void**)&p_xdf, g_xd_f);
    cudaGetSymbolAddress((void**)&p_yf,  g_y_f);

    cudaFuncSetAttribute(k_mma<EPI_NONE>,     cudaFuncAttributeMaxDynamicSharedMemorySize, SMEM_DYN);
    cudaFuncSetAttribute(k_mma<EPI_SOFTPLUS>, cudaFuncAttributeMaxDynamicSharedMemorySize, SMEM_DYN);
    cudaFuncSetAttribute(k_mma<EPI_HALF>,     cudaFuncAttributeMaxDynamicSharedMemorySize, SMEM_DYN);

    // ---- mega convert job table ----
    CvtJobs J;
    int idx = 0, cum = 0;
    auto add = [&](const float* s, __half* d, int n) {
        J.src[idx] = s; J.dst[idx] = d; J.cum[idx] = cum; cum += n/16; idx++;
    };
    J.cum[0] = 0;
    add(emb, p_ef, VOCAB*DM);
    for (int i = 0; i < NLAYER; i++) {
        add(W_in_l + (size_t)i*DI*DM, p_wlr + (size_t)i*2*DI*DM,           DI*DM);
        add(W_in_r + (size_t)i*DI*DM, p_wlr + (size_t)i*2*DI*DM + DI*DM,   DI*DM);
        add(W_x    + (size_t)i*96*DI, p_wx  + (size_t)i*96*DI,             96*DI);
        add(W_dt   + (size_t)i*DI*DR, p_wdt + (size_t)i*DI*DR,             DI*DR);
        add(W_out  + (size_t)i*DM*DI, p_wo  + (size_t)i*DM*DI,             DM*DI);
    }
    J.cum[NSEG] = cum;

    k_cvt_all<<<2368, 256>>>(J);                                   // 0
    k_embed<<<TT, 256>>>(ids, emb);                                // 1

    for (int i = 0; i < NLAYER; i++) {
        const float* cw  = conv_w + (size_t)i*DI*DC;
        const float* cb  = conv_b + (size_t)i*DI;
        const float* Al  = A_log  + (size_t)i*DI*DS;
        const float* Dpi = Dp     + (size_t)i*DI;
        const float* nw  = norm_w + (size_t)i*DM;
        __half* wlr = p_wlr + (size_t)i*2*DI*DM;
        __half* wx  = p_wx  + (size_t)i*96*DI;
        __half* wdt = p_wdt + (size_t)i*DI*DR;
        __half* wo  = p_wo  + (size_t)i*DM*DI;

        k_rmsnorm<<<TT, 256>>>(p_x, nw, p_xnf);                    // 2 (i=0)
        // 3 (i=0): fused in-proj GEMM, fp16 output <-- ncu capture control
        k_mma<EPI_HALF><<<dim3(TT/128, 2*DI/128, 1), 256, SMEM_DYN>>>(
            p_xnf, DM, wlr, DM, (float*)p_irh, 2*DI, TT, 2*DI, DM, nullptr);

        k_conv_silu<<<(TT*DI/4 + 255)/256, 256>>>(cw, cb);

        // x_dbl = u @ Wx^T  split-K x8 (Kslice=256)
        k_mma<EPI_NONE><<<dim3(TT/128, 1, 8), 256, SMEM_DYN>>>(
            p_uf, DI, wx, DI, p_part, 96, TT, 96, DI/8, nullptr);
        k_redx<<<(TT*96 + 255)/256, 256>>>(p_part);

        // delta = softplus(x_dbl[:, :64] @ Wdt^T)  (K=64)
        k_mma<EPI_SOFTPLUS><<<dim3(TT/128, DI/128, 1), 256, SMEM_DYN>>>(
            p_xdf, 96, wdt, DR, p_dlt, DI, TT, DI, DR, nullptr);

        k_scan<<<(BB*DI)/16, 256>>>(Al, Dpi);

        // out-proj split-K x2 (Kslice=1024) + residual reduce
        k_mma<EPI_NONE><<<dim3(TT/128, DM/128, 2), 256, SMEM_DYN>>>(
            p_yf, DI, wo, DI, p_part, DM, TT, DM, DI/2, nullptr);
        k_redadd<<<(TT*DM + 255)/256, 256>>>(p_part);
    }

    // final norm + logits
    k_rmsnorm<<<TT, 256>>>(p_x, norm_f_w, p_xnf);
    k_mma<EPI_NONE><<<dim3(TT/128, VOCAB/128, 1), 256, SMEM_DYN>>>(
        p_xnf, DM, p_ef, DM, out, VOCAB, TT, VOCAB, DM, nullptr);
}